// round 9
// baseline (speedup 1.0000x reference)
#include <cuda_runtime.h>
#include <math.h>
#include <stdint.h>

#define THREADS   128
#define IMGS      128          // images per block, 2 per thread
#define NP        129          // float4 stride per v-row (odd -> conflict-free)
#define PX_F4     (14 * NP)    // 1806 float4, single buffer
#define W_FLOATS  7840
#define SMEM_FLOATS (PX_F4 * 4 + W_FLOATS + 16)   // 15080 floats = 60.3 KB

typedef unsigned long long ull;

__device__ __forceinline__ void fma2(ull &acc, ull a, ull b) {
    asm("fma.rn.f32x2 %0, %1, %2, %0;" : "+l"(acc) : "l"(a), "l"(b));
}
__device__ __forceinline__ ull pack2(float lo, float hi) {
    ull r; asm("mov.b64 %0, {%1, %2};" : "=l"(r) : "f"(lo), "f"(hi)); return r;
}
__device__ __forceinline__ float2 unpack2(ull v) {
    float lo, hi; asm("mov.b64 {%0, %1}, %2;" : "=f"(lo), "=f"(hi) : "l"(v));
    return make_float2(lo, hi);
}

// FMA-pipe cosine: magic-add range reduction to [-pi,pi], deg-14 even Taylor.
// |err| <= ~4.3e-6 for |x| <= 6.3 (inputs are N(0,1)). All coeffs are FFMA imms.
__device__ __forceinline__ float pcos(float x) {
    float t = fmaf(x, 0.15915494309189535f, 12582912.0f);   // x/2pi + 1.5*2^23
    float n = t - 12582912.0f;                               // rint(x/2pi)
    float y = fmaf(n, -6.28318548202514648f, x);             // x - n*2pi_hi
    y = fmaf(n, 1.7484555043e-7f, y);                        // - n*2pi_lo
    float u = y * y;
    float p = -1.1470745e-11f;
    p = fmaf(p, u, 2.0876757e-9f);
    p = fmaf(p, u, -2.7557319e-7f);
    p = fmaf(p, u, 2.4801587e-5f);
    p = fmaf(p, u, -1.3888889e-3f);
    p = fmaf(p, u, 4.1666668e-2f);
    p = fmaf(p, u, -0.5f);
    p = fmaf(p, u, 1.0f);
    return p;
}

// one patch-row tile, two images (slots p and p+64), cols CB..CB+6
template<int CB>
__device__ __forceinline__ void compute_tile(const float4* __restrict__ px,
                                             const float*  __restrict__ s_W,
                                             int r, int p,
                                             ull* accA, ull* accB)
{
    const ulonglong2* wbase = (const ulonglong2*)s_W + r * 14;
    #pragma unroll
    for (int cc = 0; cc < 7; cc++) {
        const int c  = CB + cc;          // compile-time
        const int vA = c >> 1;           // float4 shared by cols 2vA, 2vA+1
        const int vB = 7 + vA;
        float4 a0 = px[vA * NP + p];         // img0, row 2r
        float4 a1 = px[vA * NP + 64 + p];    // img1, row 2r
        float4 b0 = px[vB * NP + p];         // img0, row 2r+1
        float4 b1 = px[vB * NP + 64 + p];    // img1, row 2r+1
        float x00_0, x01_0, x10_0, x11_0, x00_1, x01_1, x10_1, x11_1;
        if ((c & 1) == 0) {
            x00_0 = a0.x; x01_0 = a0.y; x10_0 = b0.x; x11_0 = b0.y;
            x00_1 = a1.x; x01_1 = a1.y; x10_1 = b1.x; x11_1 = b1.y;
        } else {
            x00_0 = a0.z; x01_0 = a0.w; x10_0 = b0.z; x11_0 = b0.w;
            x00_1 = a1.z; x01_1 = a1.w; x10_1 = b1.z; x11_1 = b1.w;
        }
        // split the 8 cosines: 4 on MUFU, 4 on the FMA pipe
        float e0a = __cosf(x00_0);
        float e1a = e0a * __cosf(x01_0);
        float e2a = e1a * pcos(x10_0);
        float e3a = e2a * pcos(x11_0);
        float e0b = __cosf(x00_1);
        float e1b = e0b * __cosf(x01_1);
        float e2b = e1b * pcos(x10_1);
        float e3b = e2b * pcos(x11_1);
        ull eA01 = pack2(e0a, e1a), eA23 = pack2(e2a, e3a);
        ull eB01 = pack2(e0b, e1b), eB23 = pack2(e2b, e3b);
        const ulonglong2* wrow = wbase + c;
        #pragma unroll
        for (int o = 0; o < 10; o++) {
            ulonglong2 w = wrow[o * 196];    // one uniform LDS.128 serves 2 images
            fma2(accA[o], eA01, w.x);
            fma2(accA[o], eA23, w.y);
            fma2(accB[o], eB01, w.x);
            fma2(accB[o], eB23, w.y);
        }
    }
}

__global__ void __launch_bounds__(THREADS, 3)
quanv_kernel(const float* __restrict__ x,
             const float* __restrict__ W,
             const float* __restrict__ b,
             float* __restrict__ out)
{
    extern __shared__ float smem[];
    float4* s_px = (float4*)smem;              // [14][NP] float4, single buffer
    float*  s_W  = smem + PX_F4 * 4;           // 7840 floats
    float*  s_b  = s_W + W_FLOATS;
    float*  s_mg = smem;                       // epilogue merge aliases px buffer

    const int tid   = threadIdx.x;
    const int p     = tid & 63;       // image-pair index (imgs 2p, 2p+1)
    const int chalf = tid >> 6;       // 0: cols 0..6, 1: cols 7..13 (warp-uniform)

    const long imgBase = (long)blockIdx.x * IMGS;
    const float* xg = x + imgBase * 784;

    // staging map (r-invariant): 14 float4 granules per thread
    int srcF[14], dstI[14];
    #pragma unroll
    for (int it = 0; it < 14; it++) {
        int j   = tid + it * THREADS;   // 0..1791 = 128 imgs x 14 vec4
        int img = j / 14;
        int v   = j - img * 14;
        int pos = ((img & 1) << 6) | (img >> 1);   // pair-split permutation
        srcF[it] = img * 784 + v * 4;   // + r*56 per tile
        dstI[it] = v * NP + pos;
    }

    // W (+ b) into shared
    {
        const float4* Wg = (const float4*)W;
        float4* Ws = (float4*)s_W;
        #pragma unroll 4
        for (int i = tid; i < W_FLOATS / 4; i += THREADS) Ws[i] = Wg[i];
        if (tid < 10) s_b[tid] = b[tid];
    }

    // prefetch tile 0 into registers
    float4 stage[14];
    #pragma unroll
    for (int it = 0; it < 14; it++)
        stage[it] = *(const float4*)(xg + srcF[it]);
    __syncthreads();    // W ready

    ull accA[10], accB[10];
    #pragma unroll
    for (int o = 0; o < 10; o++) { accA[o] = 0ull; accB[o] = 0ull; }

    #pragma unroll 1
    for (int r = 0; r < 14; r++) {
        // store staged tile (14 STS.128)
        #pragma unroll
        for (int it = 0; it < 14; it++) s_px[dstI[it]] = stage[it];
        __syncthreads();

        // prefetch next tile — LDG latency hidden behind compute
        if (r < 13) {
            const float* srcT = xg + (r + 1) * 56;
            #pragma unroll
            for (int it = 0; it < 14; it++)
                stage[it] = *(const float4*)(srcT + srcF[it]);
        }

        if (chalf == 0) compute_tile<0>(s_px, s_W, r, p, accA, accB);
        else            compute_tile<7>(s_px, s_W, r, p, accA, accB);
        __syncthreads();
    }

    // reduce f32x2 (even/odd k) lanes
    float sA[10], sB[10];
    #pragma unroll
    for (int o = 0; o < 10; o++) {
        float2 a = unpack2(accA[o]); sA[o] = a.x + a.y;
        float2 c = unpack2(accB[o]); sB[o] = c.x + c.y;
    }

    // merge the two column-halves via shared (stride 21 per image slot)
    if (chalf == 1) {
        #pragma unroll
        for (int o = 0; o < 10; o++) {
            s_mg[p * 42 + o]      = sA[o];
            s_mg[p * 42 + 21 + o] = sB[o];
        }
    }
    __syncthreads();

    if (chalf == 0) {
        float l[20];
        #pragma unroll
        for (int o = 0; o < 10; o++) {
            l[o]      = sA[o] + s_mg[p * 42 + o]      + s_b[o];
            l[10 + o] = sB[o] + s_mg[p * 42 + 21 + o] + s_b[o];
        }
        #pragma unroll
        for (int im = 0; im < 2; im++) {
            float m = -INFINITY;
            #pragma unroll
            for (int o = 0; o < 10; o++) m = fmaxf(m, l[im * 10 + o]);
            float s = 0.f;
            #pragma unroll
            for (int o = 0; o < 10; o++) s += __expf(l[im * 10 + o] - m);
            float lse = m + __logf(s);
            #pragma unroll
            for (int o = 0; o < 10; o++) l[im * 10 + o] -= lse;
        }
        float4* op = (float4*)(out + (imgBase + 2 * p) * 10);   // 20 floats, 16B aligned
        #pragma unroll
        for (int q = 0; q < 5; q++)
            op[q] = make_float4(l[q * 4], l[q * 4 + 1], l[q * 4 + 2], l[q * 4 + 3]);
    }
}

extern "C" void kernel_launch(void* const* d_in, const int* in_sizes, int n_in,
                              void* d_out, int out_size)
{
    const float* x = (const float*)d_in[0];
    const float* W = (const float*)d_in[1];
    const float* b = (const float*)d_in[2];
    float* out = (float*)d_out;

    const int B = in_sizes[0] / 784;                  // 65536
    const int grid = B / IMGS;                        // 512
    const size_t smem = SMEM_FLOATS * sizeof(float);  // 60.3 KB

    cudaFuncSetAttribute(quanv_kernel,
                         cudaFuncAttributeMaxDynamicSharedMemorySize, (int)smem);
    quanv_kernel<<<grid, THREADS, smem>>>(x, W, b, out);
}